// round 8
// baseline (speedup 1.0000x reference)
#include <cuda_runtime.h>
#include <math.h>

#define T_ 200
#define N_ 256
#define H_ 128
#define G_ 512   // 4*H
#define V_ 50000

#define TB 10          // time-block size (divides 200, even)
#define NBLK (T_/TB)   // 20 blocks
#define NB 4           // sequences per cluster
#define NCLUST (N_/NB) // 64 clusters -> 128 CTAs
#define HD 64          // h-dims owned per CTA

typedef unsigned long long ull;

// Scratch (static device globals — allocation-free per harness rules)
__device__ float g_wx[(size_t)T_ * N_ * G_];    // 104.8 MB
__device__ float g_hhist[(size_t)T_ * N_ * H_]; // 26.2 MB
__device__ float g_chist[(size_t)T_ * N_ * H_]; // 26.2 MB
__device__ float g_hmean[N_ * H_];

// fast transcendentals (error ~1e-6, far under the 1e-3 gate)
__device__ __forceinline__ float fsig(float x) {
    return __fdividef(1.0f, 1.0f + __expf(-x));
}
__device__ __forceinline__ float ftanh(float x) {
    float a = fabsf(x);
    float e = __expf(-2.0f * a);
    float r = __fdividef(1.0f - e, 1.0f + e);
    return copysignf(r, x);
}

// ---- packed f32x2 helpers ----
__device__ __forceinline__ ull pk2(float x, float y) {
    ull r; asm("mov.b64 %0,{%1,%2};" : "=l"(r) : "f"(x), "f"(y)); return r;
}
__device__ __forceinline__ ull f2fma(ull a, ull b, ull c) {
    ull d; asm("fma.rn.f32x2 %0,%1,%2,%3;" : "=l"(d) : "l"(a), "l"(b), "l"(c)); return d;
}
__device__ __forceinline__ float2 up2(ull v) {
    float lo, hi; asm("mov.b64 {%0,%1},%2;" : "=f"(lo), "=f"(hi) : "l"(v));
    float2 r; r.x = lo; r.y = hi; return r;
}
__device__ __forceinline__ unsigned smem_u32(const void* p) {
    unsigned a;
    asm("{ .reg .u64 t; cvta.to.shared.u64 t, %1; cvt.u32.u64 %0, t; }" : "=r"(a) : "l"(p));
    return a;
}
__device__ __forceinline__ void st_peer32(unsigned addr, float v, unsigned peer_rank) {
    unsigned pa;
    asm("mapa.shared::cluster.u32 %0, %1, %2;" : "=r"(pa) : "r"(addr), "r"(peer_rank));
    asm volatile("st.shared::cluster.f32 [%0], %1;" :: "r"(pa), "f"(v) : "memory");
}
#define CLUSTER_SYNC() do { \
    asm volatile("barrier.cluster.arrive.aligned;" ::: "memory"); \
    asm volatile("barrier.cluster.wait.aligned;"   ::: "memory"); \
} while (0)

// ---------------------------------------------------------------------------
// Kernel 1: Wx = emb[seq] @ W + b.  64x64 tile, 2x8 register tile (fewer pk2 +
// LDS per FMA than 4x4); As k-quad vectorized; Bs reads broadcast-dedup'd.
// ---------------------------------------------------------------------------
__global__ void __launch_bounds__(256) wx_kernel(const int* __restrict__ seq,
                                                 const float* __restrict__ emb,
                                                 const float* __restrict__ W,
                                                 const float* __restrict__ b)
{
    extern __shared__ float sm[];
    float* As = sm;                 // [64][132]
    float* Bs = sm + 64 * 132;      // [128][64]
    int*   ridx = (int*)(Bs + 128 * 64);

    const int tid = threadIdx.x;
    const int bc = blockIdx.x;
    const int br = blockIdx.y;

    if (tid < 64) ridx[tid] = seq[br * 64 + tid];
    __syncthreads();

    for (int p = tid; p < 64 * 32; p += 256) {
        int r = p >> 5, kq = p & 31;
        float4 v = *(const float4*)(emb + (size_t)ridx[r] * H_ + kq * 4);
        float* dst = As + r * 132 + kq * 4;
        dst[0] = v.x; dst[1] = v.y; dst[2] = v.z; dst[3] = v.w;
    }
    for (int p = tid; p < 128 * 16; p += 256) {
        int k = p >> 4, cq = p & 15;
        *(float4*)(Bs + k * 64 + cq * 4) = *(const float4*)(W + k * G_ + bc * 64 + cq * 4);
    }
    __syncthreads();

    const int ty = tid >> 3, tx = tid & 7;
    const int r0 = ty * 2, c0 = tx * 8;
    ull acc[2][4];
    #pragma unroll
    for (int i = 0; i < 2; i++)
        #pragma unroll
        for (int j = 0; j < 4; j++) acc[i][j] = 0ull;

    #pragma unroll 4
    for (int k4 = 0; k4 < 32; ++k4) {
        const int kb = k4 * 4;
        float a[2][4];
        #pragma unroll
        for (int i = 0; i < 2; i++)
            *(float4*)a[i] = *(const float4*)(As + (r0 + i) * 132 + kb);
        #pragma unroll
        for (int kk = 0; kk < 4; ++kk) {
            ulonglong2 b01 = *(const ulonglong2*)(Bs + (kb + kk) * 64 + c0);
            ulonglong2 b23 = *(const ulonglong2*)(Bs + (kb + kk) * 64 + c0 + 4);
            #pragma unroll
            for (int i = 0; i < 2; i++) {
                ull ap = pk2(a[i][kk], a[i][kk]);
                acc[i][0] = f2fma(ap, b01.x, acc[i][0]);
                acc[i][1] = f2fma(ap, b01.y, acc[i][1]);
                acc[i][2] = f2fma(ap, b23.x, acc[i][2]);
                acc[i][3] = f2fma(ap, b23.y, acc[i][3]);
            }
        }
    }

    float4 bi0 = *(const float4*)(b + bc * 64 + c0);
    float4 bi1 = *(const float4*)(b + bc * 64 + c0 + 4);
    #pragma unroll
    for (int i = 0; i < 2; i++) {
        int row = br * 64 + r0 + i;
        float2 p0 = up2(acc[i][0]), p1 = up2(acc[i][1]);
        float2 p2 = up2(acc[i][2]), p3 = up2(acc[i][3]);
        float4 o0, o1;
        o0.x = p0.x + bi0.x; o0.y = p0.y + bi0.y; o0.z = p1.x + bi0.z; o0.w = p1.y + bi0.w;
        o1.x = p2.x + bi1.x; o1.y = p2.y + bi1.y; o1.z = p3.x + bi1.z; o1.w = p3.y + bi1.w;
        __stcs((float4*)(g_wx + (size_t)row * G_ + bc * 64 + c0), o0);
        __stcs((float4*)(g_wx + (size_t)row * G_ + bc * 64 + c0 + 4), o1);
    }
}

// ---------------------------------------------------------------------------
// Kernel 2: recurrence v7 — v6 structure with the spill fixed: phase B GEMV is
// FULLY unrolled so u[128] stays register-resident (partial unroll demoted it
// to local memory in v6 — the R7 regression).
// ---------------------------------------------------------------------------
__global__ void __launch_bounds__(256, 1) __cluster_dims__(2, 1, 1)
rec5_kernel(const float* __restrict__ mask,
            const float* __restrict__ topo,
            const float* __restrict__ U)
{
    extern __shared__ float sm[];
    float* topoT = sm;                       // [4][200][12] = 9600
    float* Ph    = topoT + 4 * 200 * 12;     // [TB][4][64]
    float* Pc    = Ph + TB * NB * HD;        // [TB][4][64]
    float* ringh = Pc + TB * NB * HD;        // [TB][4][64]
    float* ringc = ringh + TB * NB * HD;
    float* hsumP = ringc + TB * NB * HD;     // [2][128][4]
    float* gl    = hsumP + 2 * 128 * 4;      // [4][256]
    float* smask = gl + 4 * 256;             // [TB][4]

    const int tid  = threadIdx.x;
    const int wid  = tid >> 5;
    const int lane = tid & 31;
    const unsigned rank = blockIdx.x & 1;
    const int clu = blockIdx.x >> 1;
    const int n0  = clu * NB;
    const int d0  = rank * HD;               // my global dim base

    // my local gate column
    const int lc = tid;
    const int gg = lc >> 6, dl = lc & 63;
    const int gc = gg * 128 + d0 + dl;       // global gate column

    // ---- U column into registers (statically indexed everywhere) ----
    float u[H_];
    #pragma unroll
    for (int i = 0; i < H_; ++i) u[i] = U[(size_t)i * G_ + gc];

    const int ej = tid >> 6;                 // seq (0..3)
    const int ed = tid & 63;                 // my local dim (0..63)
    const unsigned hsumP_base = smem_u32(hsumP);
    const unsigned peer = rank ^ 1;
    float hacc = 0.0f, lsum = 0.0f;

    for (int k = 0; k < NBLK; ++k) {
        const int t0 = k * TB;
        const int plen = t0 + TB;

        __syncthreads();   // prior block's readers done before overwriting topoT/smask

        // ---- topo prefix + mask block ----
        for (int r_ = wid; r_ < TB * NB; r_ += 8) {
            int tt = r_ / NB, j = r_ % NB;
            const float* src = topo + ((size_t)(t0 + tt) * N_ + (n0 + j)) * T_;
            for (int tp = lane; tp < plen; tp += 32)
                topoT[(j * 200 + tp) * 12 + tt] = __ldcs(src + tp);
        }
        if (tid < TB * NB) {
            int tt = tid >> 2, j = tid & 3;
            smask[tt * NB + j] = mask[(t0 + tt) * N_ + n0 + j];
        }
        __syncthreads();

        // ---- prologue: P[tt][j][my dims] from global history ----
        if (k == 0) {
            for (int i = tid; i < 2 * TB * NB * HD; i += 256) Ph[i] = 0.0f;
        } else {
            const int j  = wid >> 1;
            const int hc = wid & 1;
            const float* hist = hc ? g_chist : g_hhist;
            float* P = hc ? Pc : Ph;
            const int dl2 = lane * 2;
            ull acc[5][2];
            #pragma unroll
            for (int pr = 0; pr < 5; pr++) { acc[pr][0] = 0ull; acc[pr][1] = 0ull; }
            #pragma unroll 4
            for (int tp = 0; tp < t0; ++tp) {
                float2 hv = *(const float2*)(hist + ((size_t)tp * N_ + n0 + j) * H_ + d0 + dl2);
                const float* tr = topoT + (j * 200 + tp) * 12;
                ulonglong2 wA = *(const ulonglong2*)(tr);
                ulonglong2 wB = *(const ulonglong2*)(tr + 4);
                ull        wC = *(const ull*)(tr + 8);
                ull h0 = pk2(hv.x, hv.x), h1 = pk2(hv.y, hv.y);
                acc[0][0] = f2fma(wA.x, h0, acc[0][0]); acc[0][1] = f2fma(wA.x, h1, acc[0][1]);
                acc[1][0] = f2fma(wA.y, h0, acc[1][0]); acc[1][1] = f2fma(wA.y, h1, acc[1][1]);
                acc[2][0] = f2fma(wB.x, h0, acc[2][0]); acc[2][1] = f2fma(wB.x, h1, acc[2][1]);
                acc[3][0] = f2fma(wB.y, h0, acc[3][0]); acc[3][1] = f2fma(wB.y, h1, acc[3][1]);
                acc[4][0] = f2fma(wC,   h0, acc[4][0]); acc[4][1] = f2fma(wC,   h1, acc[4][1]);
            }
            #pragma unroll
            for (int pr = 0; pr < 5; pr++) {
                float2 a0 = up2(acc[pr][0]);
                float2 a1 = up2(acc[pr][1]);
                P[((2 * pr)     * NB + j) * HD + dl2]     = a0.x;
                P[((2 * pr + 1) * NB + j) * HD + dl2]     = a0.y;
                P[((2 * pr)     * NB + j) * HD + dl2 + 1] = a1.x;
                P[((2 * pr + 1) * NB + j) * HD + dl2 + 1] = a1.y;
            }
        }
        __syncthreads();

        // ---- initial publish for tt=0 (buf 0) ----
        float ac_cur;
        {
            float ah = Ph[(0 * NB + ej) * HD + ed];
            ac_cur   = Pc[(0 * NB + ej) * HD + ed];
            unsigned addr = hsumP_base + (unsigned)(((d0 + ed) * 4 + ej) * 4);
            asm volatile("st.shared.f32 [%0], %1;" :: "r"(addr), "f"(ah) : "memory");
            st_peer32(addr, ah, peer);
        }

        // ---- sequential steps: 2 barriers per step ----
        for (int tt = 0; tt < TB; ++tt) {
            const int t = t0 + tt;
            const int buf = tt & 1;

            // prefetch Wx (consumed at end of phase B; hides under barrier+GEMV)
            const float* wbase = g_wx + ((size_t)t * N_ + n0) * G_ + gc;
            float w0 = __ldcs(wbase);
            float w1 = __ldcs(wbase + G_);
            float w2 = __ldcs(wbase + 2 * G_);
            float w3 = __ldcs(wbase + 3 * G_);

            CLUSTER_SYNC();   // both halves of hsum published & visible

            // phase B: gates(lc) = sum_i hsum[i][:]*u[i] + Wx
            // FULL unroll — mandatory so u[i] is statically indexed (registers)
            {
                ull a01 = 0ull, a23 = 0ull;
                const float* hb = hsumP + buf * 512;
                #pragma unroll
                for (int i = 0; i < H_; ++i) {
                    ulonglong2 hh = *(const ulonglong2*)(hb + i * 4);
                    ull uu = pk2(u[i], u[i]);
                    a01 = f2fma(uu, hh.x, a01);
                    a23 = f2fma(uu, hh.y, a23);
                }
                float2 r01 = up2(a01), r23 = up2(a23);
                gl[0 * 256 + lc] = r01.x + w0;
                gl[1 * 256 + lc] = r01.y + w1;
                gl[2 * 256 + lc] = r23.x + w2;
                gl[3 * 256 + lc] = r23.y + w3;
            }
            __syncthreads();

            // merged phase C + A(tt+1): cell, ring write (self-owned), next agg,
            // publish — no extra barrier (taps only read self-written entries)
            {
                float m  = smask[tt * NB + ej];
                float ig = fsig(gl[ej * 256 + ed]);
                float fg = fsig(gl[ej * 256 + 64 + ed]);
                float og = fsig(gl[ej * 256 + 128 + ed]);
                float gt = ftanh(gl[ej * 256 + 192 + ed]);
                float c  = m * (fg * ac_cur + ig * gt);
                float h  = m * (og * ftanh(c));
                ringh[(tt * NB + ej) * HD + ed] = h;
                ringc[(tt * NB + ej) * HD + ed] = c;
                g_hhist[((size_t)t * N_ + n0 + ej) * H_ + d0 + ed] = h;
                g_chist[((size_t)t * N_ + n0 + ej) * H_ + d0 + ed] = c;
                hacc += m * h;
                lsum += m;

                if (tt + 1 < TB) {
                    float ah = Ph[((tt + 1) * NB + ej) * HD + ed];
                    ac_cur   = Pc[((tt + 1) * NB + ej) * HD + ed];
                    const float* tb2 = topoT + (ej * 200 + t0) * 12 + (tt + 1);
                    for (int s = 0; s <= tt; ++s) {
                        float w = tb2[s * 12];
                        ah     += w * ringh[(s * NB + ej) * HD + ed];
                        ac_cur += w * ringc[(s * NB + ej) * HD + ed];
                    }
                    unsigned addr = hsumP_base
                        + (unsigned)((((buf ^ 1) * 128 + d0 + ed) * 4 + ej) * 4);
                    asm volatile("st.shared.f32 [%0], %1;" :: "r"(addr), "f"(ah) : "memory");
                    st_peer32(addr, ah, peer);
                }
            }
        }
    }

    g_hmean[(n0 + ej) * H_ + d0 + ed] = hacc / lsum;
    CLUSTER_SYNC();   // no CTA exits while peer DSMEM stores may be in flight
}

// ---------------------------------------------------------------------------
// Kernel 3: out = h_mean @ W_out + b_out   (k-quad vectorized As)
// ---------------------------------------------------------------------------
__global__ void __launch_bounds__(256) out_kernel(const float* __restrict__ Wout,
                                                  const float* __restrict__ bout,
                                                  float* __restrict__ out)
{
    extern __shared__ float sm[];
    float* As = sm;                 // [64][132]
    float* Bs = sm + 64 * 132;      // [128][64]

    const int tid = threadIdx.x;
    const int bc = blockIdx.x;
    const int br = blockIdx.y;
    const int cbase = bc * 64;

    for (int p = tid; p < 64 * 32; p += 256) {
        int r = p >> 5, kq = p & 31;
        float4 v = *(const float4*)(g_hmean + (size_t)(br * 64 + r) * H_ + kq * 4);
        float* dst = As + r * 132 + kq * 4;
        dst[0] = v.x; dst[1] = v.y; dst[2] = v.z; dst[3] = v.w;
    }
    for (int p = tid; p < 128 * 16; p += 256) {
        int k = p >> 4, cq = p & 15;
        int c = cbase + cq * 4;
        float4 v = make_float4(0.f, 0.f, 0.f, 0.f);
        if (c < V_) v = *(const float4*)(Wout + (size_t)k * V_ + c);
        *(float4*)(Bs + k * 64 + cq * 4) = v;
    }
    __syncthreads();

    const int ty = tid >> 3, tx = tid & 7;
    const int r0 = ty * 2, c0 = tx * 8;
    ull acc[2][4];
    #pragma unroll
    for (int i = 0; i < 2; i++)
        #pragma unroll
        for (int j = 0; j < 4; j++) acc[i][j] = 0ull;

    #pragma unroll 4
    for (int k4 = 0; k4 < 32; ++k4) {
        const int kb = k4 * 4;
        float a[2][4];
        #pragma unroll
        for (int i = 0; i < 2; i++)
            *(float4*)a[i] = *(const float4*)(As + (r0 + i) * 132 + kb);
        #pragma unroll
        for (int kk = 0; kk < 4; ++kk) {
            ulonglong2 b01 = *(const ulonglong2*)(Bs + (kb + kk) * 64 + c0);
            ulonglong2 b23 = *(const ulonglong2*)(Bs + (kb + kk) * 64 + c0 + 4);
            #pragma unroll
            for (int i = 0; i < 2; i++) {
                ull ap = pk2(a[i][kk], a[i][kk]);
                acc[i][0] = f2fma(ap, b01.x, acc[i][0]);
                acc[i][1] = f2fma(ap, b01.y, acc[i][1]);
                acc[i][2] = f2fma(ap, b23.x, acc[i][2]);
                acc[i][3] = f2fma(ap, b23.y, acc[i][3]);
            }
        }
    }

    int c = cbase + c0;
    if (c < V_) {
        float4 bi0 = *(const float4*)(bout + c);
        float4 bi1 = *(const float4*)(bout + c + 4);
        #pragma unroll
        for (int i = 0; i < 2; i++) {
            int row = br * 64 + r0 + i;
            float2 p0 = up2(acc[i][0]), p1 = up2(acc[i][1]);
            float2 p2 = up2(acc[i][2]), p3 = up2(acc[i][3]);
            float4 o0, o1;
            o0.x = p0.x + bi0.x; o0.y = p0.y + bi0.y; o0.z = p1.x + bi0.z; o0.w = p1.y + bi0.w;
            o1.x = p2.x + bi1.x; o1.y = p2.y + bi1.y; o1.z = p3.x + bi1.z; o1.w = p3.y + bi1.w;
            *(float4*)(out + (size_t)row * V_ + c) = o0;
            *(float4*)(out + (size_t)row * V_ + c + 4) = o1;
        }
    }
}

// ---------------------------------------------------------------------------
extern "C" void kernel_launch(void* const* d_in, const int* in_sizes, int n_in,
                              void* d_out, int out_size)
{
    const int*   seq  = (const int*)d_in[0];
    const float* mask = (const float*)d_in[1];
    const float* topo = (const float*)d_in[2];
    const float* W    = (const float*)d_in[3];
    const float* U    = (const float*)d_in[4];
    const float* b    = (const float*)d_in[5];
    const float* emb  = (const float*)d_in[6];
    const float* Wout = (const float*)d_in[7];
    const float* bout = (const float*)d_in[8];
    float* out = (float*)d_out;

    const int smem_gemm = (64 * 132 + 128 * 64 + 64) * 4;     // 66,816 B
    const int smem_rec  = (4 * 200 * 12 + 4 * TB * NB * HD
                           + 2 * 128 * 4 + 4 * 256 + TB * NB + 24) * 4;  // ~88 KB

    cudaFuncSetAttribute(wx_kernel,   cudaFuncAttributeMaxDynamicSharedMemorySize, smem_gemm);
    cudaFuncSetAttribute(out_kernel,  cudaFuncAttributeMaxDynamicSharedMemorySize, smem_gemm);
    cudaFuncSetAttribute(rec5_kernel, cudaFuncAttributeMaxDynamicSharedMemorySize, smem_rec);

    wx_kernel<<<dim3(G_ / 64, (T_ * N_) / 64), 256, smem_gemm>>>(seq, emb, W, b);
    rec5_kernel<<<2 * NCLUST, 256, smem_rec>>>(mask, topo, U);
    out_kernel<<<dim3((V_ + 63) / 64, N_ / 64), 256, smem_gemm>>>(Wout, bout, out);
}

// round 9
// speedup vs baseline: 1.3619x; 1.3619x over previous
#include <cuda_runtime.h>
#include <math.h>

#define T_ 200
#define N_ 256
#define H_ 128
#define G_ 512   // 4*H
#define V_ 50000

#define TB 10          // time-block size (divides 200, even)
#define NBLK (T_/TB)   // 20 blocks
#define NB 4           // sequences per cluster
#define NCLUST (N_/NB) // 64 clusters -> 128 CTAs
#define HD 64          // h-dims owned per CTA

typedef unsigned long long ull;

// Scratch (static device globals — allocation-free per harness rules)
__device__ float g_wx[(size_t)T_ * N_ * G_];    // 104.8 MB
__device__ float g_hhist[(size_t)T_ * N_ * H_]; // 26.2 MB
__device__ float g_chist[(size_t)T_ * N_ * H_]; // 26.2 MB
__device__ float g_hmean[N_ * H_];

// fast transcendentals (error ~1e-6, far under the 1e-3 gate)
__device__ __forceinline__ float fsig(float x) {
    return __fdividef(1.0f, 1.0f + __expf(-x));
}
__device__ __forceinline__ float ftanh(float x) {
    float a = fabsf(x);
    float e = __expf(-2.0f * a);
    float r = __fdividef(1.0f - e, 1.0f + e);
    return copysignf(r, x);
}

// ---- packed f32x2 helpers ----
__device__ __forceinline__ ull pk2(float x, float y) {
    ull r; asm("mov.b64 %0,{%1,%2};" : "=l"(r) : "f"(x), "f"(y)); return r;
}
__device__ __forceinline__ ull f2fma(ull a, ull b, ull c) {
    ull d; asm("fma.rn.f32x2 %0,%1,%2,%3;" : "=l"(d) : "l"(a), "l"(b), "l"(c)); return d;
}
__device__ __forceinline__ float2 up2(ull v) {
    float lo, hi; asm("mov.b64 {%0,%1},%2;" : "=f"(lo), "=f"(hi) : "l"(v));
    float2 r; r.x = lo; r.y = hi; return r;
}
__device__ __forceinline__ unsigned smem_u32(const void* p) {
    unsigned a;
    asm("{ .reg .u64 t; cvta.to.shared.u64 t, %1; cvt.u32.u64 %0, t; }" : "=r"(a) : "l"(p));
    return a;
}
__device__ __forceinline__ void st_peer32(unsigned addr, float v, unsigned peer_rank) {
    unsigned pa;
    asm("mapa.shared::cluster.u32 %0, %1, %2;" : "=r"(pa) : "r"(addr), "r"(peer_rank));
    asm volatile("st.shared::cluster.f32 [%0], %1;" :: "r"(pa), "f"(v) : "memory");
}
#define CLUSTER_SYNC() do { \
    asm volatile("barrier.cluster.arrive.aligned;" ::: "memory"); \
    asm volatile("barrier.cluster.wait.aligned;"   ::: "memory"); \
} while (0)

// ---------------------------------------------------------------------------
// Kernel 1: Wx = emb[seq] @ W + b.  64x64 tile, 4x4 register tile, k-quad
// vectorized As (measured 184us — best configuration).
// ---------------------------------------------------------------------------
__global__ void __launch_bounds__(256) wx_kernel(const int* __restrict__ seq,
                                                 const float* __restrict__ emb,
                                                 const float* __restrict__ W,
                                                 const float* __restrict__ b)
{
    extern __shared__ float sm[];
    float* As = sm;                 // [64][132]
    float* Bs = sm + 64 * 132;      // [128][64]
    int*   ridx = (int*)(Bs + 128 * 64);

    const int tid = threadIdx.x;
    const int bc = blockIdx.x;
    const int br = blockIdx.y;

    if (tid < 64) ridx[tid] = seq[br * 64 + tid];
    __syncthreads();

    for (int p = tid; p < 64 * 32; p += 256) {
        int r = p >> 5, kq = p & 31;
        float4 v = *(const float4*)(emb + (size_t)ridx[r] * H_ + kq * 4);
        float* dst = As + r * 132 + kq * 4;
        dst[0] = v.x; dst[1] = v.y; dst[2] = v.z; dst[3] = v.w;
    }
    for (int p = tid; p < 128 * 16; p += 256) {
        int k = p >> 4, cq = p & 15;
        *(float4*)(Bs + k * 64 + cq * 4) = *(const float4*)(W + k * G_ + bc * 64 + cq * 4);
    }
    __syncthreads();

    const int ty = tid >> 4, tx = tid & 15;
    const int r0 = ty * 4, c0 = tx * 4;
    ull a01[4], a23[4];
    #pragma unroll
    for (int i = 0; i < 4; i++) { a01[i] = 0ull; a23[i] = 0ull; }

    #pragma unroll 4
    for (int k4 = 0; k4 < 32; ++k4) {
        const int kb = k4 * 4;
        float a[4][4];
        #pragma unroll
        for (int i = 0; i < 4; i++)
            *(float4*)a[i] = *(const float4*)(As + (r0 + i) * 132 + kb);
        #pragma unroll
        for (int kk = 0; kk < 4; ++kk) {
            ulonglong2 bv = *(const ulonglong2*)(Bs + (kb + kk) * 64 + c0);
            #pragma unroll
            for (int i = 0; i < 4; i++) {
                ull ap = pk2(a[i][kk], a[i][kk]);
                a01[i] = f2fma(ap, bv.x, a01[i]);
                a23[i] = f2fma(ap, bv.y, a23[i]);
            }
        }
    }

    float4 bias = *(const float4*)(b + bc * 64 + c0);
    #pragma unroll
    for (int i = 0; i < 4; i++) {
        int row = br * 64 + r0 + i;
        float2 p01 = up2(a01[i]), p23 = up2(a23[i]);
        float4 o;
        o.x = p01.x + bias.x;
        o.y = p01.y + bias.y;
        o.z = p23.x + bias.z;
        o.w = p23.y + bias.w;
        __stcs((float4*)(g_wx + (size_t)row * G_ + bc * 64 + c0), o);
    }
}

// ---------------------------------------------------------------------------
// Kernel 2: recurrence v8 — R5's proven 3-phase structure with:
//  * U pre-packed as 64 ull pairs (no per-step pk2 in the GEMV)
//  * hsum published scalar in [buf][seq][i] layout; GEMV reads i-quads (LDS.128)
//  * fast sigmoid/tanh in the cell
//  * hist STGs batched into a block epilogue (off the serial path)
// ---------------------------------------------------------------------------
__global__ void __launch_bounds__(256, 1) __cluster_dims__(2, 1, 1)
rec6_kernel(const float* __restrict__ mask,
            const float* __restrict__ topo,
            const float* __restrict__ U)
{
    extern __shared__ float sm[];
    float* topoT = sm;                       // [4][200][12] = 9600
    float* Ph    = topoT + 4 * 200 * 12;     // [TB][4][64]
    float* Pc    = Ph + TB * NB * HD;        // [TB][4][64]
    float* ringh = Pc + TB * NB * HD;        // [TB][4][64]
    float* ringc = ringh + TB * NB * HD;
    float* hsumP = ringc + TB * NB * HD;     // [2][4][128]  (buf, seq, i)
    float* csum  = hsumP + 2 * NB * H_;      // [4][64]
    float* gl    = csum + NB * HD;           // [4][256]

    const int tid  = threadIdx.x;
    const int wid  = tid >> 5;
    const int lane = tid & 31;
    const unsigned rank = blockIdx.x & 1;
    const int clu = blockIdx.x >> 1;
    const int n0  = clu * NB;
    const int d0  = rank * HD;               // my global dim base

    // my local gate column
    const int lc = tid;
    const int gg = lc >> 6, dl = lc & 63;
    const int gc = gg * 128 + d0 + dl;       // global gate column

    // ---- U column pre-packed into 64 ull register pairs ----
    ull up[H_ / 2];
    #pragma unroll
    for (int q = 0; q < H_ / 2; ++q)
        up[q] = pk2(U[(size_t)(2 * q) * G_ + gc], U[(size_t)(2 * q + 1) * G_ + gc]);

    const int ej = tid >> 6;                 // seq (0..3)
    const int ed = tid & 63;                 // my local dim (0..63)
    const unsigned hsumP_base = smem_u32(hsumP);
    const unsigned peer = rank ^ 1;
    float hacc = 0.0f, lsum = 0.0f;

    for (int k = 0; k < NBLK; ++k) {
        const int t0 = k * TB;
        const int plen = t0 + TB;

        // ---- topo prefix (streamed; prior readers done at last step's bar) ----
        for (int r_ = wid; r_ < TB * NB; r_ += 8) {
            int tt = r_ / NB, j = r_ % NB;
            const float* src = topo + ((size_t)(t0 + tt) * N_ + (n0 + j)) * T_;
            for (int tp = lane; tp < plen; tp += 32)
                topoT[(j * 200 + tp) * 12 + tt] = __ldcs(src + tp);
        }
        __syncthreads();

        // ---- prologue: P[tt][j][my dims] from global history ----
        if (k == 0) {
            for (int i = tid; i < 2 * TB * NB * HD; i += 256) Ph[i] = 0.0f;
        } else {
            const int j  = wid >> 1;
            const int hc = wid & 1;
            const float* hist = hc ? g_chist : g_hhist;
            float* P = hc ? Pc : Ph;
            const int dl2 = lane * 2;
            ull acc[5][2];
            #pragma unroll
            for (int pr = 0; pr < 5; pr++) { acc[pr][0] = 0ull; acc[pr][1] = 0ull; }
            #pragma unroll 4
            for (int tp = 0; tp < t0; ++tp) {
                float2 hv = *(const float2*)(hist + ((size_t)tp * N_ + n0 + j) * H_ + d0 + dl2);
                const float* tr = topoT + (j * 200 + tp) * 12;
                ulonglong2 wA = *(const ulonglong2*)(tr);
                ulonglong2 wB = *(const ulonglong2*)(tr + 4);
                ull        wC = *(const ull*)(tr + 8);
                ull h0 = pk2(hv.x, hv.x), h1 = pk2(hv.y, hv.y);
                acc[0][0] = f2fma(wA.x, h0, acc[0][0]); acc[0][1] = f2fma(wA.x, h1, acc[0][1]);
                acc[1][0] = f2fma(wA.y, h0, acc[1][0]); acc[1][1] = f2fma(wA.y, h1, acc[1][1]);
                acc[2][0] = f2fma(wB.x, h0, acc[2][0]); acc[2][1] = f2fma(wB.x, h1, acc[2][1]);
                acc[3][0] = f2fma(wB.y, h0, acc[3][0]); acc[3][1] = f2fma(wB.y, h1, acc[3][1]);
                acc[4][0] = f2fma(wC,   h0, acc[4][0]); acc[4][1] = f2fma(wC,   h1, acc[4][1]);
            }
            #pragma unroll
            for (int pr = 0; pr < 5; pr++) {
                float2 a0 = up2(acc[pr][0]);
                float2 a1 = up2(acc[pr][1]);
                P[((2 * pr)     * NB + j) * HD + dl2]     = a0.x;
                P[((2 * pr + 1) * NB + j) * HD + dl2]     = a0.y;
                P[((2 * pr)     * NB + j) * HD + dl2 + 1] = a1.x;
                P[((2 * pr + 1) * NB + j) * HD + dl2 + 1] = a1.y;
            }
        }
        __syncthreads();

        // ---- sequential steps (R5 3-phase flow) ----
        for (int tt = 0; tt < TB; ++tt) {
            const int t = t0 + tt;
            const int buf = t & 1;

            // prefetch Wx + mask (consumed after the barrier; latency hides
            // under phase A + cluster sync)
            const float* wbase = g_wx + ((size_t)t * N_ + n0) * G_ + gc;
            float w0 = __ldcs(wbase);
            float w1 = __ldcs(wbase + G_);
            float w2 = __ldcs(wbase + 2 * G_);
            float w3 = __ldcs(wbase + 3 * G_);
            float m  = mask[t * N_ + n0 + ej];

            // phase A: aggregate my dims; publish hsum scalar ([buf][ej][i])
            {
                float ah = Ph[(tt * NB + ej) * HD + ed];
                float ac = Pc[(tt * NB + ej) * HD + ed];
                const float* tb2 = topoT + (ej * 200 + t0) * 12 + tt;
                for (int s = 0; s < tt; ++s) {
                    float w = tb2[s * 12];
                    ah += w * ringh[(s * NB + ej) * HD + ed];
                    ac += w * ringc[(s * NB + ej) * HD + ed];
                }
                csum[ej * HD + ed] = ac;
                unsigned addr = hsumP_base
                    + (unsigned)((buf * NB * H_ + ej * H_ + d0 + ed) * 4);
                asm volatile("st.shared.f32 [%0], %1;" :: "r"(addr), "f"(ah) : "memory");
                st_peer32(addr, ah, peer);
            }
            CLUSTER_SYNC();   // both halves published & visible (release-ordered)

            // phase B: gates(lc) = sum_i hsum[s][i]*u[i] + Wx
            // u pre-packed in regs; hsum broadcast LDS.128 over i-quads.
            {
                ull acc0 = 0ull, acc1 = 0ull, acc2 = 0ull, acc3 = 0ull;
                const float* hb = hsumP + buf * NB * H_;
                #pragma unroll
                for (int q4 = 0; q4 < H_ / 4; ++q4) {
                    ulonglong2 h0 = *(const ulonglong2*)(hb + 0 * H_ + q4 * 4);
                    ulonglong2 h1 = *(const ulonglong2*)(hb + 1 * H_ + q4 * 4);
                    ulonglong2 h2 = *(const ulonglong2*)(hb + 2 * H_ + q4 * 4);
                    ulonglong2 h3 = *(const ulonglong2*)(hb + 3 * H_ + q4 * 4);
                    ull ua = up[2 * q4], ub = up[2 * q4 + 1];
                    acc0 = f2fma(h0.x, ua, acc0); acc0 = f2fma(h0.y, ub, acc0);
                    acc1 = f2fma(h1.x, ua, acc1); acc1 = f2fma(h1.y, ub, acc1);
                    acc2 = f2fma(h2.x, ua, acc2); acc2 = f2fma(h2.y, ub, acc2);
                    acc3 = f2fma(h3.x, ua, acc3); acc3 = f2fma(h3.y, ub, acc3);
                }
                float2 p0 = up2(acc0), p1 = up2(acc1), p2 = up2(acc2), p3 = up2(acc3);
                gl[0 * 256 + lc] = p0.x + p0.y + w0;
                gl[1 * 256 + lc] = p1.x + p1.y + w1;
                gl[2 * 256 + lc] = p2.x + p2.y + w2;
                gl[3 * 256 + lc] = p3.x + p3.y + w3;
            }
            __syncthreads();

            // phase C: cell for my dims (fast transcendentals); ring only —
            // global hist flushed in the block epilogue
            {
                float ig = fsig(gl[ej * 256 + ed]);
                float fg = fsig(gl[ej * 256 + 64 + ed]);
                float og = fsig(gl[ej * 256 + 128 + ed]);
                float gt = ftanh(gl[ej * 256 + 192 + ed]);
                float c  = m * (fg * csum[ej * HD + ed] + ig * gt);
                float h  = m * (og * ftanh(c));
                ringh[(tt * NB + ej) * HD + ed] = h;
                ringc[(tt * NB + ej) * HD + ed] = c;
                hacc += m * h;
                lsum += m;
            }
            __syncthreads();
        }

        // ---- block epilogue: flush ring to global history (batched, coalesced)
        #pragma unroll
        for (int s = 0; s < TB; ++s) {
            g_hhist[((size_t)(t0 + s) * N_ + n0 + ej) * H_ + d0 + ed] =
                ringh[(s * NB + ej) * HD + ed];
            g_chist[((size_t)(t0 + s) * N_ + n0 + ej) * H_ + d0 + ed] =
                ringc[(s * NB + ej) * HD + ed];
        }
        __syncthreads();   // stores visible block-wide before next prologue reads
    }

    g_hmean[(n0 + ej) * H_ + d0 + ed] = hacc / lsum;
    CLUSTER_SYNC();   // no CTA exits while peer DSMEM stores may be in flight
}

// ---------------------------------------------------------------------------
// Kernel 3: out = h_mean @ W_out + b_out   (4x4 tile, k-quad vectorized As)
// ---------------------------------------------------------------------------
__global__ void __launch_bounds__(256) out_kernel(const float* __restrict__ Wout,
                                                  const float* __restrict__ bout,
                                                  float* __restrict__ out)
{
    extern __shared__ float sm[];
    float* As = sm;                 // [64][132]
    float* Bs = sm + 64 * 132;      // [128][64]

    const int tid = threadIdx.x;
    const int bc = blockIdx.x;
    const int br = blockIdx.y;
    const int cbase = bc * 64;

    for (int p = tid; p < 64 * 32; p += 256) {
        int r = p >> 5, kq = p & 31;
        float4 v = *(const float4*)(g_hmean + (size_t)(br * 64 + r) * H_ + kq * 4);
        float* dst = As + r * 132 + kq * 4;
        dst[0] = v.x; dst[1] = v.y; dst[2] = v.z; dst[3] = v.w;
    }
    for (int p = tid; p < 128 * 16; p += 256) {
        int k = p >> 4, cq = p & 15;
        int c = cbase + cq * 4;
        float4 v = make_float4(0.f, 0.f, 0.f, 0.f);
        if (c < V_) v = *(const float4*)(Wout + (size_t)k * V_ + c);
        *(float4*)(Bs + k * 64 + cq * 4) = v;
    }
    __syncthreads();

    const int ty = tid >> 4, tx = tid & 15;
    const int r0 = ty * 4, c0 = tx * 4;
    ull a01[4], a23[4];
    #pragma unroll
    for (int i = 0; i < 4; i++) { a01[i] = 0ull; a23[i] = 0ull; }

    #pragma unroll 4
    for (int k4 = 0; k4 < 32; ++k4) {
        const int kb = k4 * 4;
        float a[4][4];
        #pragma unroll
        for (int i = 0; i < 4; i++)
            *(float4*)a[i] = *(const float4*)(As + (r0 + i) * 132 + kb);
        #pragma unroll
        for (int kk = 0; kk < 4; ++kk) {
            ulonglong2 bv = *(const ulonglong2*)(Bs + (kb + kk) * 64 + c0);
            #pragma unroll
            for (int i = 0; i < 4; i++) {
                ull ap = pk2(a[i][kk], a[i][kk]);
                a01[i] = f2fma(ap, bv.x, a01[i]);
                a23[i] = f2fma(ap, bv.y, a23[i]);
            }
        }
    }

    int c = cbase + c0;
    if (c < V_) {
        float4 bias = *(const float4*)(bout + c);
        #pragma unroll
        for (int i = 0; i < 4; i++) {
            int row = br * 64 + r0 + i;
            float2 p01 = up2(a01[i]), p23 = up2(a23[i]);
            float4 o;
            o.x = p01.x + bias.x;
            o.y = p01.y + bias.y;
            o.z = p23.x + bias.z;
            o.w = p23.y + bias.w;
            *(float4*)(out + (size_t)row * V_ + c) = o;
        }
    }
}

// ---------------------------------------------------------------------------
extern "C" void kernel_launch(void* const* d_in, const int* in_sizes, int n_in,
                              void* d_out, int out_size)
{
    const int*   seq  = (const int*)d_in[0];
    const float* mask = (const float*)d_in[1];
    const float* topo = (const float*)d_in[2];
    const float* W    = (const float*)d_in[3];
    const float* U    = (const float*)d_in[4];
    const float* b    = (const float*)d_in[5];
    const float* emb  = (const float*)d_in[6];
    const float* Wout = (const float*)d_in[7];
    const float* bout = (const float*)d_in[8];
    float* out = (float*)d_out;

    const int smem_gemm = (64 * 132 + 128 * 64 + 64) * 4;     // 66,816 B
    const int smem_rec  = (4 * 200 * 12 + 4 * TB * NB * HD
                           + 2 * NB * H_ + NB * HD + NB * 256) * 4;  // ~88.6 KB

    cudaFuncSetAttribute(wx_kernel,   cudaFuncAttributeMaxDynamicSharedMemorySize, smem_gemm);
    cudaFuncSetAttribute(out_kernel,  cudaFuncAttributeMaxDynamicSharedMemorySize, smem_gemm);
    cudaFuncSetAttribute(rec6_kernel, cudaFuncAttributeMaxDynamicSharedMemorySize, smem_rec);

    wx_kernel<<<dim3(G_ / 64, (T_ * N_) / 64), 256, smem_gemm>>>(seq, emb, W, b);
    rec6_kernel<<<2 * NCLUST, 256, smem_rec>>>(mask, topo, U);
    out_kernel<<<dim3((V_ + 63) / 64, N_ / 64), 256, smem_gemm>>>(Wout, bout, out);
}

// round 10
// speedup vs baseline: 1.5976x; 1.1731x over previous
#include <cuda_runtime.h>
#include <math.h>

#define T_ 200
#define N_ 256
#define H_ 128
#define G_ 512   // 4*H
#define V_ 50000

#define TB 10          // time-block size (divides 200, even)
#define NBLK (T_/TB)   // 20 blocks
#define NB 4           // sequences per cluster
#define NCLUST (N_/NB) // 64 clusters -> 128 CTAs
#define HD 64          // h-dims owned per CTA

typedef unsigned long long ull;

// Scratch (static device globals — allocation-free per harness rules)
__device__ float g_wx[(size_t)T_ * N_ * G_];    // 104.8 MB
__device__ float g_hhist[(size_t)T_ * N_ * H_]; // 26.2 MB
__device__ float g_chist[(size_t)T_ * N_ * H_]; // 26.2 MB
__device__ float g_hmean[N_ * H_];

// fast transcendentals (error ~1e-6, far under the 1e-3 gate)
__device__ __forceinline__ float fsig(float x) {
    return __fdividef(1.0f, 1.0f + __expf(-x));
}
__device__ __forceinline__ float ftanh(float x) {
    float a = fabsf(x);
    float e = __expf(-2.0f * a);
    float r = __fdividef(1.0f - e, 1.0f + e);
    return copysignf(r, x);
}

// ---- packed f32x2 helpers ----
__device__ __forceinline__ ull pk2(float x, float y) {
    ull r; asm("mov.b64 %0,{%1,%2};" : "=l"(r) : "f"(x), "f"(y)); return r;
}
__device__ __forceinline__ ull f2fma(ull a, ull b, ull c) {
    ull d; asm("fma.rn.f32x2 %0,%1,%2,%3;" : "=l"(d) : "l"(a), "l"(b), "l"(c)); return d;
}
__device__ __forceinline__ float2 up2(ull v) {
    float lo, hi; asm("mov.b64 {%0,%1},%2;" : "=f"(lo), "=f"(hi) : "l"(v));
    float2 r; r.x = lo; r.y = hi; return r;
}
__device__ __forceinline__ unsigned smem_u32(const void* p) {
    unsigned a;
    asm("{ .reg .u64 t; cvta.to.shared.u64 t, %1; cvt.u32.u64 %0, t; }" : "=r"(a) : "l"(p));
    return a;
}
__device__ __forceinline__ unsigned mapa_peer(unsigned addr, unsigned peer_rank) {
    unsigned pa;
    asm("mapa.shared::cluster.u32 %0, %1, %2;" : "=r"(pa) : "r"(addr), "r"(peer_rank));
    return pa;
}
#define CLUSTER_SYNC() do { \
    asm volatile("barrier.cluster.arrive.aligned;" ::: "memory"); \
    asm volatile("barrier.cluster.wait.aligned;"   ::: "memory"); \
} while (0)

// mbarrier primitives
#define MBAR_INIT(addr, cnt) \
    asm volatile("mbarrier.init.shared.b64 [%0], %1;" :: "r"(addr), "r"(cnt) : "memory")
#define MBAR_ARRIVE(addr) \
    asm volatile("mbarrier.arrive.shared.b64 _, [%0];" :: "r"(addr) : "memory")
#define MBAR_EXPECT_TX(addr, bytes) \
    asm volatile("mbarrier.arrive.expect_tx.shared.b64 _, [%0], %1;" :: "r"(addr), "r"(bytes) : "memory")
// acquire at CLUSTER scope: orders peer st.async data before our reads
#define MBAR_WAIT_PARITY_CLUSTER(addr, par) do { \
    unsigned _m = (addr), _p = (par), _done; \
    asm volatile( \
        "{\n\t.reg .pred p;\n\t" \
        "mbarrier.try_wait.parity.acquire.cluster.shared::cta.b64 p, [%1], %2;\n\t" \
        "selp.b32 %0, 1, 0, p;\n\t}" : "=r"(_done) : "r"(_m), "r"(_p) : "memory"); \
    if (!_done) { \
        asm volatile( \
            "{\n\t.reg .pred P1;\n\t" \
            "WL_%=:\n\t" \
            "mbarrier.try_wait.parity.acquire.cluster.shared::cta.b64 P1, [%0], %1, 0x989680;\n\t" \
            "@P1 bra.uni WD_%=;\n\t" \
            "bra.uni WL_%=;\n\t" \
            "WD_%=:\n\t}" :: "r"(_m), "r"(_p) : "memory"); \
    } \
} while (0)
// async store to peer smem, tx-counted on peer's mbarrier
__device__ __forceinline__ void stasync_peer(unsigned paddr, float v, unsigned pbar) {
    asm volatile(
        "st.async.weak.shared::cluster.mbarrier::complete_tx::bytes.b32 [%0], %1, [%2];"
        :: "r"(paddr), "r"(__float_as_uint(v)), "r"(pbar) : "memory");
}

// ---------------------------------------------------------------------------
// Kernel 1: Wx = emb[seq] @ W + b.  64x64 tile, 4x4 register tile, k-quad
// vectorized As (measured 184-185us).
// ---------------------------------------------------------------------------
__global__ void __launch_bounds__(256) wx_kernel(const int* __restrict__ seq,
                                                 const float* __restrict__ emb,
                                                 const float* __restrict__ W,
                                                 const float* __restrict__ b)
{
    extern __shared__ float sm[];
    float* As = sm;                 // [64][132]
    float* Bs = sm + 64 * 132;      // [128][64]
    int*   ridx = (int*)(Bs + 128 * 64);

    const int tid = threadIdx.x;
    const int bc = blockIdx.x;
    const int br = blockIdx.y;

    if (tid < 64) ridx[tid] = seq[br * 64 + tid];
    __syncthreads();

    for (int p = tid; p < 64 * 32; p += 256) {
        int r = p >> 5, kq = p & 31;
        float4 v = *(const float4*)(emb + (size_t)ridx[r] * H_ + kq * 4);
        float* dst = As + r * 132 + kq * 4;
        dst[0] = v.x; dst[1] = v.y; dst[2] = v.z; dst[3] = v.w;
    }
    for (int p = tid; p < 128 * 16; p += 256) {
        int k = p >> 4, cq = p & 15;
        *(float4*)(Bs + k * 64 + cq * 4) = *(const float4*)(W + k * G_ + bc * 64 + cq * 4);
    }
    __syncthreads();

    const int ty = tid >> 4, tx = tid & 15;
    const int r0 = ty * 4, c0 = tx * 4;
    ull a01[4], a23[4];
    #pragma unroll
    for (int i = 0; i < 4; i++) { a01[i] = 0ull; a23[i] = 0ull; }

    #pragma unroll 4
    for (int k4 = 0; k4 < 32; ++k4) {
        const int kb = k4 * 4;
        float a[4][4];
        #pragma unroll
        for (int i = 0; i < 4; i++)
            *(float4*)a[i] = *(const float4*)(As + (r0 + i) * 132 + kb);
        #pragma unroll
        for (int kk = 0; kk < 4; ++kk) {
            ulonglong2 bv = *(const ulonglong2*)(Bs + (kb + kk) * 64 + c0);
            #pragma unroll
            for (int i = 0; i < 4; i++) {
                ull ap = pk2(a[i][kk], a[i][kk]);
                a01[i] = f2fma(ap, bv.x, a01[i]);
                a23[i] = f2fma(ap, bv.y, a23[i]);
            }
        }
    }

    float4 bias = *(const float4*)(b + bc * 64 + c0);
    #pragma unroll
    for (int i = 0; i < 4; i++) {
        int row = br * 64 + r0 + i;
        float2 p01 = up2(a01[i]), p23 = up2(a23[i]);
        float4 o;
        o.x = p01.x + bias.x;
        o.y = p01.y + bias.y;
        o.z = p23.x + bias.z;
        o.w = p23.y + bias.w;
        __stcs((float4*)(g_wx + (size_t)row * G_ + bc * 64 + c0), o);
    }
}

// ---------------------------------------------------------------------------
// Kernel 2: recurrence v9 — cluster exchange via mbarrier + st.async
// (no per-step cluster.sync / no DSMEM drain / no L1 flush).
// Per step: 1 mbar-wait + 1 syncthreads. Cell+next-agg merged (self-owned
// ring taps). U pre-packed in registers. csum carried in a register.
// ---------------------------------------------------------------------------
__global__ void __launch_bounds__(256, 1) __cluster_dims__(2, 1, 1)
rec7_kernel(const float* __restrict__ mask,
            const float* __restrict__ topo,
            const float* __restrict__ U)
{
    extern __shared__ float sm[];
    // [0..4): two mbarriers (ull each)
    float* topoT = sm + 4;                   // [4][200][12] = 9600
    float* Ph    = topoT + 4 * 200 * 12;     // [TB][4][64]
    float* Pc    = Ph + TB * NB * HD;
    float* ringh = Pc + TB * NB * HD;        // [TB][4][64]
    float* ringc = ringh + TB * NB * HD;
    float* hsumP = ringc + TB * NB * HD;     // [2][4][128]  (buf, seq, i)
    float* gl    = hsumP + 2 * NB * H_;      // [4][256]
    float* smask = gl + 4 * 256;             // [TB][4]

    const int tid  = threadIdx.x;
    const int wid  = tid >> 5;
    const int lane = tid & 31;
    const unsigned rank = blockIdx.x & 1;
    const int clu = blockIdx.x >> 1;
    const int n0  = clu * NB;
    const int d0  = rank * HD;               // my global dim base

    const int lc = tid;
    const int gg = lc >> 6, dl = lc & 63;
    const int gc = gg * 128 + d0 + dl;       // global gate column

    // ---- U column pre-packed into 64 ull register pairs ----
    ull up[H_ / 2];
    #pragma unroll
    for (int q = 0; q < H_ / 2; ++q)
        up[q] = pk2(U[(size_t)(2 * q) * G_ + gc], U[(size_t)(2 * q + 1) * G_ + gc]);

    const int ej = tid >> 6;                 // seq (0..3)
    const int ed = tid & 63;                 // my local dim (0..63)
    const unsigned peer = rank ^ 1;

    // mbarriers: 257 arrives (256 threads + 1 expect_tx-arrive) + 1024 tx bytes
    const unsigned bar0 = smem_u32(sm);
    const unsigned bar1 = bar0 + 8;
    if (tid == 0) { MBAR_INIT(bar0, 257); MBAR_INIT(bar1, 257); }
    __syncthreads();
    CLUSTER_SYNC();   // peer bars initialized before any st.async targets them

    const unsigned mybar[2]  = { bar0, bar1 };
    const unsigned pbar[2]   = { mapa_peer(bar0, peer), mapa_peer(bar1, peer) };
    // hsum slot for my (ej,ed) value, per buf; peer slot at same offset
    const unsigned slot0 = smem_u32(hsumP) + (unsigned)((ej * H_ + d0 + ed) * 4);
    const unsigned slot1 = slot0 + (unsigned)(NB * H_ * 4);
    const unsigned myslot[2] = { slot0, slot1 };
    const unsigned pslot[2]  = { mapa_peer(slot0, peer), mapa_peer(slot1, peer) };

    float hacc = 0.0f, lsum = 0.0f;

    for (int k = 0; k < NBLK; ++k) {
        const int t0 = k * TB;
        const int plen = t0 + TB;

        // ---- topo prefix + mask (prior readers done at epilogue syncthreads) ----
        for (int r_ = wid; r_ < TB * NB; r_ += 8) {
            int tt = r_ / NB, j = r_ % NB;
            const float* src = topo + ((size_t)(t0 + tt) * N_ + (n0 + j)) * T_;
            for (int tp = lane; tp < plen; tp += 32)
                topoT[(j * 200 + tp) * 12 + tt] = __ldcs(src + tp);
        }
        if (tid < TB * NB) {
            int tt = tid >> 2, j = tid & 3;
            smask[tt * NB + j] = mask[(t0 + tt) * N_ + n0 + j];
        }
        __syncthreads();

        // ---- prologue: P[tt][j][my dims] from global history ----
        if (k == 0) {
            for (int i = tid; i < 2 * TB * NB * HD; i += 256) Ph[i] = 0.0f;
        } else {
            const int j  = wid >> 1;
            const int hc = wid & 1;
            const float* hist = hc ? g_chist : g_hhist;
            float* P = hc ? Pc : Ph;
            const int dl2 = lane * 2;
            ull acc[5][2];
            #pragma unroll
            for (int pr = 0; pr < 5; pr++) { acc[pr][0] = 0ull; acc[pr][1] = 0ull; }
            #pragma unroll 4
            for (int tp = 0; tp < t0; ++tp) {
                float2 hv = *(const float2*)(hist + ((size_t)tp * N_ + n0 + j) * H_ + d0 + dl2);
                const float* tr = topoT + (j * 200 + tp) * 12;
                ulonglong2 wA = *(const ulonglong2*)(tr);
                ulonglong2 wB = *(const ulonglong2*)(tr + 4);
                ull        wC = *(const ull*)(tr + 8);
                ull h0 = pk2(hv.x, hv.x), h1 = pk2(hv.y, hv.y);
                acc[0][0] = f2fma(wA.x, h0, acc[0][0]); acc[0][1] = f2fma(wA.x, h1, acc[0][1]);
                acc[1][0] = f2fma(wA.y, h0, acc[1][0]); acc[1][1] = f2fma(wA.y, h1, acc[1][1]);
                acc[2][0] = f2fma(wB.x, h0, acc[2][0]); acc[2][1] = f2fma(wB.x, h1, acc[2][1]);
                acc[3][0] = f2fma(wB.y, h0, acc[3][0]); acc[3][1] = f2fma(wB.y, h1, acc[3][1]);
                acc[4][0] = f2fma(wC,   h0, acc[4][0]); acc[4][1] = f2fma(wC,   h1, acc[4][1]);
            }
            #pragma unroll
            for (int pr = 0; pr < 5; pr++) {
                float2 a0 = up2(acc[pr][0]);
                float2 a1 = up2(acc[pr][1]);
                P[((2 * pr)     * NB + j) * HD + dl2]     = a0.x;
                P[((2 * pr + 1) * NB + j) * HD + dl2]     = a0.y;
                P[((2 * pr)     * NB + j) * HD + dl2 + 1] = a1.x;
                P[((2 * pr + 1) * NB + j) * HD + dl2 + 1] = a1.y;
            }
        }
        __syncthreads();

        // ---- publish for tt=0 of this block (buf = t0&1 = 0 since TB even) ----
        float ac_cur;
        {
            const int b0 = t0 & 1;
            float ah = Ph[(0 * NB + ej) * HD + ed];
            ac_cur   = Pc[(0 * NB + ej) * HD + ed];
            asm volatile("st.shared.f32 [%0], %1;" :: "r"(myslot[b0]), "f"(ah) : "memory");
            MBAR_ARRIVE(mybar[b0]);
            stasync_peer(pslot[b0], ah, pbar[b0]);
            if (tid == 0) MBAR_EXPECT_TX(mybar[b0], 1024);
        }

        // ---- sequential steps: 1 mbar-wait + 1 syncthreads per step ----
        for (int tt = 0; tt < TB; ++tt) {
            const int t = t0 + tt;
            const int buf = t & 1;
            const unsigned par = (unsigned)((t >> 1) & 1);

            // prefetch Wx (before the wait; consumed at end of phase B)
            const float* wbase = g_wx + ((size_t)t * N_ + n0) * G_ + gc;
            float w0 = __ldcs(wbase);
            float w1 = __ldcs(wbase + G_);
            float w2 = __ldcs(wbase + 2 * G_);
            float w3 = __ldcs(wbase + 3 * G_);
            float m  = smask[tt * NB + ej];

            MBAR_WAIT_PARITY_CLUSTER(mybar[buf], par);

            // phase B: gates(lc) = sum_i hsum[s][i]*u[i] + Wx
            {
                ull acc0 = 0ull, acc1 = 0ull, acc2 = 0ull, acc3 = 0ull;
                const float* hb = hsumP + buf * NB * H_;
                #pragma unroll
                for (int q4 = 0; q4 < H_ / 4; ++q4) {
                    ulonglong2 h0 = *(const ulonglong2*)(hb + 0 * H_ + q4 * 4);
                    ulonglong2 h1 = *(const ulonglong2*)(hb + 1 * H_ + q4 * 4);
                    ulonglong2 h2 = *(const ulonglong2*)(hb + 2 * H_ + q4 * 4);
                    ulonglong2 h3 = *(const ulonglong2*)(hb + 3 * H_ + q4 * 4);
                    ull ua = up[2 * q4], ub = up[2 * q4 + 1];
                    acc0 = f2fma(h0.x, ua, acc0); acc0 = f2fma(h0.y, ub, acc0);
                    acc1 = f2fma(h1.x, ua, acc1); acc1 = f2fma(h1.y, ub, acc1);
                    acc2 = f2fma(h2.x, ua, acc2); acc2 = f2fma(h2.y, ub, acc2);
                    acc3 = f2fma(h3.x, ua, acc3); acc3 = f2fma(h3.y, ub, acc3);
                }
                float2 p0 = up2(acc0), p1 = up2(acc1), p2 = up2(acc2), p3 = up2(acc3);
                gl[0 * 256 + lc] = p0.x + p0.y + w0;
                gl[1 * 256 + lc] = p1.x + p1.y + w1;
                gl[2 * 256 + lc] = p2.x + p2.y + w2;
                gl[3 * 256 + lc] = p3.x + p3.y + w3;
            }
            __syncthreads();

            // merged phase C + A(tt+1): cell, self-owned ring writes, next agg,
            // publish via arrive + st.async (no barrier needed in between)
            {
                float ig = fsig(gl[ej * 256 + ed]);
                float fg = fsig(gl[ej * 256 + 64 + ed]);
                float og = fsig(gl[ej * 256 + 128 + ed]);
                float gt = ftanh(gl[ej * 256 + 192 + ed]);
                float c  = m * (fg * ac_cur + ig * gt);
                float h  = m * (og * ftanh(c));
                ringh[(tt * NB + ej) * HD + ed] = h;
                ringc[(tt * NB + ej) * HD + ed] = c;
                hacc += m * h;
                lsum += m;

                if (tt + 1 < TB) {
                    const int nbuf = (t + 1) & 1;
                    float ah = Ph[((tt + 1) * NB + ej) * HD + ed];
                    ac_cur   = Pc[((tt + 1) * NB + ej) * HD + ed];
                    const float* tb2 = topoT + (ej * 200 + t0) * 12 + (tt + 1);
                    for (int s = 0; s <= tt; ++s) {
                        float w = tb2[s * 12];
                        ah     += w * ringh[(s * NB + ej) * HD + ed];
                        ac_cur += w * ringc[(s * NB + ej) * HD + ed];
                    }
                    asm volatile("st.shared.f32 [%0], %1;" :: "r"(myslot[nbuf]), "f"(ah) : "memory");
                    MBAR_ARRIVE(mybar[nbuf]);
                    stasync_peer(pslot[nbuf], ah, pbar[nbuf]);
                    if (tid == 0) MBAR_EXPECT_TX(mybar[nbuf], 1024);
                }
            }
        }

        // ---- block epilogue: flush ring to global history (batched) ----
        #pragma unroll
        for (int s = 0; s < TB; ++s) {
            g_hhist[((size_t)(t0 + s) * N_ + n0 + ej) * H_ + d0 + ed] =
                ringh[(s * NB + ej) * HD + ed];
            g_chist[((size_t)(t0 + s) * N_ + n0 + ej) * H_ + d0 + ed] =
                ringc[(s * NB + ej) * HD + ed];
        }
        __syncthreads();   // flush visible + topoT readers done before next block
    }

    g_hmean[(n0 + ej) * H_ + d0 + ed] = hacc / lsum;
    CLUSTER_SYNC();   // no CTA exits while peer st.async may be in flight
}

// ---------------------------------------------------------------------------
// Kernel 3: out = h_mean @ W_out + b_out   (4x4 tile, k-quad vectorized As)
// ---------------------------------------------------------------------------
__global__ void __launch_bounds__(256) out_kernel(const float* __restrict__ Wout,
                                                  const float* __restrict__ bout,
                                                  float* __restrict__ out)
{
    extern __shared__ float sm[];
    float* As = sm;                 // [64][132]
    float* Bs = sm + 64 * 132;      // [128][64]

    const int tid = threadIdx.x;
    const int bc = blockIdx.x;
    const int br = blockIdx.y;
    const int cbase = bc * 64;

    for (int p = tid; p < 64 * 32; p += 256) {
        int r = p >> 5, kq = p & 31;
        float4 v = *(const float4*)(g_hmean + (size_t)(br * 64 + r) * H_ + kq * 4);
        float* dst = As + r * 132 + kq * 4;
        dst[0] = v.x; dst[1] = v.y; dst[2] = v.z; dst[3] = v.w;
    }
    for (int p = tid; p < 128 * 16; p += 256) {
        int k = p >> 4, cq = p & 15;
        int c = cbase + cq * 4;
        float4 v = make_float4(0.f, 0.f, 0.f, 0.f);
        if (c < V_) v = *(const float4*)(Wout + (size_t)k * V_ + c);
        *(float4*)(Bs + k * 64 + cq * 4) = v;
    }
    __syncthreads();

    const int ty = tid >> 4, tx = tid & 15;
    const int r0 = ty * 4, c0 = tx * 4;
    ull a01[4], a23[4];
    #pragma unroll
    for (int i = 0; i < 4; i++) { a01[i] = 0ull; a23[i] = 0ull; }

    #pragma unroll 4
    for (int k4 = 0; k4 < 32; ++k4) {
        const int kb = k4 * 4;
        float a[4][4];
        #pragma unroll
        for (int i = 0; i < 4; i++)
            *(float4*)a[i] = *(const float4*)(As + (r0 + i) * 132 + kb);
        #pragma unroll
        for (int kk = 0; kk < 4; ++kk) {
            ulonglong2 bv = *(const ulonglong2*)(Bs + (kb + kk) * 64 + c0);
            #pragma unroll
            for (int i = 0; i < 4; i++) {
                ull ap = pk2(a[i][kk], a[i][kk]);
                a01[i] = f2fma(ap, bv.x, a01[i]);
                a23[i] = f2fma(ap, bv.y, a23[i]);
            }
        }
    }

    int c = cbase + c0;
    if (c < V_) {
        float4 bias = *(const float4*)(bout + c);
        #pragma unroll
        for (int i = 0; i < 4; i++) {
            int row = br * 64 + r0 + i;
            float2 p01 = up2(a01[i]), p23 = up2(a23[i]);
            float4 o;
            o.x = p01.x + bias.x;
            o.y = p01.y + bias.y;
            o.z = p23.x + bias.z;
            o.w = p23.y + bias.w;
            *(float4*)(out + (size_t)row * V_ + c) = o;
        }
    }
}

// ---------------------------------------------------------------------------
extern "C" void kernel_launch(void* const* d_in, const int* in_sizes, int n_in,
                              void* d_out, int out_size)
{
    const int*   seq  = (const int*)d_in[0];
    const float* mask = (const float*)d_in[1];
    const float* topo = (const float*)d_in[2];
    const float* W    = (const float*)d_in[3];
    const float* U    = (const float*)d_in[4];
    const float* b    = (const float*)d_in[5];
    const float* emb  = (const float*)d_in[6];
    const float* Wout = (const float*)d_in[7];
    const float* bout = (const float*)d_in[8];
    float* out = (float*)d_out;

    const int smem_gemm = (64 * 132 + 128 * 64 + 64) * 4;     // 66,816 B
    const int smem_rec  = (4 + 4 * 200 * 12 + 4 * TB * NB * HD
                           + 2 * NB * H_ + NB * 256 + TB * NB + 16) * 4;  // ~88 KB

    cudaFuncSetAttribute(wx_kernel,   cudaFuncAttributeMaxDynamicSharedMemorySize, smem_gemm);
    cudaFuncSetAttribute(out_kernel,  cudaFuncAttributeMaxDynamicSharedMemorySize, smem_gemm);
    cudaFuncSetAttribute(rec7_kernel, cudaFuncAttributeMaxDynamicSharedMemorySize, smem_rec);

    wx_kernel<<<dim3(G_ / 64, (T_ * N_) / 64), 256, smem_gemm>>>(seq, emb, W, b);
    rec7_kernel<<<2 * NCLUST, 256, smem_rec>>>(mask, topo, U);
    out_kernel<<<dim3((V_ + 63) / 64, N_ / 64), 256, smem_gemm>>>(Wout, bout, out);
}

// round 11
// speedup vs baseline: 1.6270x; 1.0184x over previous
#include <cuda_runtime.h>
#include <math.h>

#define T_ 200
#define N_ 256
#define H_ 128
#define G_ 512   // 4*H
#define V_ 50000

#define TB 10          // time-block size (divides 200, even)
#define NBLK (T_/TB)   // 20 blocks
#define NB 4           // sequences per cluster
#define NCLUST (N_/NB) // 64 clusters -> 128 CTAs
#define HD 64          // h-dims owned per CTA

typedef unsigned long long ull;

// Scratch (static device globals — allocation-free per harness rules)
__device__ float g_wx[(size_t)T_ * N_ * G_];    // 104.8 MB
__device__ float g_hhist[(size_t)T_ * N_ * H_]; // 26.2 MB
__device__ float g_chist[(size_t)T_ * N_ * H_]; // 26.2 MB
__device__ float g_hmean[N_ * H_];

// fast transcendentals (error ~1e-6, far under the 1e-3 gate)
__device__ __forceinline__ float fsig(float x) {
    return __fdividef(1.0f, 1.0f + __expf(-x));
}
__device__ __forceinline__ float ftanh(float x) {
    float a = fabsf(x);
    float e = __expf(-2.0f * a);
    float r = __fdividef(1.0f - e, 1.0f + e);
    return copysignf(r, x);
}

// ---- packed f32x2 helpers ----
__device__ __forceinline__ ull pk2(float x, float y) {
    ull r; asm("mov.b64 %0,{%1,%2};" : "=l"(r) : "f"(x), "f"(y)); return r;
}
__device__ __forceinline__ ull f2fma(ull a, ull b, ull c) {
    ull d; asm("fma.rn.f32x2 %0,%1,%2,%3;" : "=l"(d) : "l"(a), "l"(b), "l"(c)); return d;
}
__device__ __forceinline__ float2 up2(ull v) {
    float lo, hi; asm("mov.b64 {%0,%1},%2;" : "=f"(lo), "=f"(hi) : "l"(v));
    float2 r; r.x = lo; r.y = hi; return r;
}
__device__ __forceinline__ unsigned smem_u32(const void* p) {
    unsigned a;
    asm("{ .reg .u64 t; cvta.to.shared.u64 t, %1; cvt.u32.u64 %0, t; }" : "=r"(a) : "l"(p));
    return a;
}
__device__ __forceinline__ unsigned mapa_peer(unsigned addr, unsigned peer_rank) {
    unsigned pa;
    asm("mapa.shared::cluster.u32 %0, %1, %2;" : "=r"(pa) : "r"(addr), "r"(peer_rank));
    return pa;
}
#define CLUSTER_SYNC() do { \
    asm volatile("barrier.cluster.arrive.aligned;" ::: "memory"); \
    asm volatile("barrier.cluster.wait.aligned;"   ::: "memory"); \
} while (0)

// mbarrier primitives (tx-only protocol: init count=1, tid0 expect_tx arrives)
#define MBAR_INIT(addr, cnt) \
    asm volatile("mbarrier.init.shared.b64 [%0], %1;" :: "r"(addr), "r"(cnt) : "memory")
#define MBAR_EXPECT_TX(addr, bytes) \
    asm volatile("mbarrier.arrive.expect_tx.shared.b64 _, [%0], %1;" :: "r"(addr), "r"(bytes) : "memory")
// acquire at CLUSTER scope: orders peer st.async data before our reads
#define MBAR_WAIT_PARITY_CLUSTER(addr, par) do { \
    unsigned _m = (addr), _p = (par), _done; \
    asm volatile( \
        "{\n\t.reg .pred p;\n\t" \
        "mbarrier.try_wait.parity.acquire.cluster.shared::cta.b64 p, [%1], %2;\n\t" \
        "selp.b32 %0, 1, 0, p;\n\t}" : "=r"(_done) : "r"(_m), "r"(_p) : "memory"); \
    if (!_done) { \
        asm volatile( \
            "{\n\t.reg .pred P1;\n\t" \
            "WL_%=:\n\t" \
            "mbarrier.try_wait.parity.acquire.cluster.shared::cta.b64 P1, [%0], %1, 0x989680;\n\t" \
            "@P1 bra.uni WD_%=;\n\t" \
            "bra.uni WL_%=;\n\t" \
            "WD_%=:\n\t}" :: "r"(_m), "r"(_p) : "memory"); \
    } \
} while (0)
// async store to peer smem, tx-counted on peer's mbarrier
__device__ __forceinline__ void stasync_peer(unsigned paddr, float v, unsigned pbar) {
    asm volatile(
        "st.async.weak.shared::cluster.mbarrier::complete_tx::bytes.b32 [%0], %1, [%2];"
        :: "r"(paddr), "r"(__float_as_uint(v)), "r"(pbar) : "memory");
}

// ---------------------------------------------------------------------------
// Kernel 1: Wx = emb[seq] @ W + b.  64x64 tile, 4x4 register tile, k-quad
// vectorized As (measured 184-185us).
// ---------------------------------------------------------------------------
__global__ void __launch_bounds__(256) wx_kernel(const int* __restrict__ seq,
                                                 const float* __restrict__ emb,
                                                 const float* __restrict__ W,
                                                 const float* __restrict__ b)
{
    extern __shared__ float sm[];
    float* As = sm;                 // [64][132]
    float* Bs = sm + 64 * 132;      // [128][64]
    int*   ridx = (int*)(Bs + 128 * 64);

    const int tid = threadIdx.x;
    const int bc = blockIdx.x;
    const int br = blockIdx.y;

    if (tid < 64) ridx[tid] = seq[br * 64 + tid];
    __syncthreads();

    for (int p = tid; p < 64 * 32; p += 256) {
        int r = p >> 5, kq = p & 31;
        float4 v = *(const float4*)(emb + (size_t)ridx[r] * H_ + kq * 4);
        float* dst = As + r * 132 + kq * 4;
        dst[0] = v.x; dst[1] = v.y; dst[2] = v.z; dst[3] = v.w;
    }
    for (int p = tid; p < 128 * 16; p += 256) {
        int k = p >> 4, cq = p & 15;
        *(float4*)(Bs + k * 64 + cq * 4) = *(const float4*)(W + k * G_ + bc * 64 + cq * 4);
    }
    __syncthreads();

    const int ty = tid >> 4, tx = tid & 15;
    const int r0 = ty * 4, c0 = tx * 4;
    ull a01[4], a23[4];
    #pragma unroll
    for (int i = 0; i < 4; i++) { a01[i] = 0ull; a23[i] = 0ull; }

    #pragma unroll 4
    for (int k4 = 0; k4 < 32; ++k4) {
        const int kb = k4 * 4;
        float a[4][4];
        #pragma unroll
        for (int i = 0; i < 4; i++)
            *(float4*)a[i] = *(const float4*)(As + (r0 + i) * 132 + kb);
        #pragma unroll
        for (int kk = 0; kk < 4; ++kk) {
            ulonglong2 bv = *(const ulonglong2*)(Bs + (kb + kk) * 64 + c0);
            #pragma unroll
            for (int i = 0; i < 4; i++) {
                ull ap = pk2(a[i][kk], a[i][kk]);
                a01[i] = f2fma(ap, bv.x, a01[i]);
                a23[i] = f2fma(ap, bv.y, a23[i]);
            }
        }
    }

    float4 bias = *(const float4*)(b + bc * 64 + c0);
    #pragma unroll
    for (int i = 0; i < 4; i++) {
        int row = br * 64 + r0 + i;
        float2 p01 = up2(a01[i]), p23 = up2(a23[i]);
        float4 o;
        o.x = p01.x + bias.x;
        o.y = p01.y + bias.y;
        o.z = p23.x + bias.z;
        o.w = p23.y + bias.w;
        __stcs((float4*)(g_wx + (size_t)row * G_ + bc * 64 + c0), o);
    }
}

// ---------------------------------------------------------------------------
// Kernel 2: recurrence v10 — tx-only mbarrier (no per-thread arrives), and
// the GEMV is split around the wait: local-half GEMV runs while the peer's
// st.async messages are in flight, peer-half GEMV after the wait.
// U registers loaded PERMUTED (local rows first) so indexing stays static.
// ---------------------------------------------------------------------------
__global__ void __launch_bounds__(256, 1) __cluster_dims__(2, 1, 1)
rec8_kernel(const float* __restrict__ mask,
            const float* __restrict__ topo,
            const float* __restrict__ U)
{
    extern __shared__ float sm[];
    // [0..4): two mbarriers (ull each)
    float* topoT = sm + 4;                   // [4][200][12] = 9600
    float* Ph    = topoT + 4 * 200 * 12;     // [TB][4][64]
    float* Pc    = Ph + TB * NB * HD;
    float* ringh = Pc + TB * NB * HD;        // [TB][4][64]
    float* ringc = ringh + TB * NB * HD;
    float* hsumP = ringc + TB * NB * HD;     // [2][4][128]  (buf, seq, i)
    float* gl    = hsumP + 2 * NB * H_;      // [4][256]
    float* smask = gl + 4 * 256;             // [TB][4]

    const int tid  = threadIdx.x;
    const int wid  = tid >> 5;
    const int lane = tid & 31;
    const unsigned rank = blockIdx.x & 1;
    const int clu = blockIdx.x >> 1;
    const int n0  = clu * NB;
    const int d0  = rank * HD;               // my dim base
    const int pd0 = d0 ^ HD;                 // peer dim base

    const int lc = tid;
    const int gg = lc >> 6, dl = lc & 63;
    const int gc = gg * 128 + d0 + dl;       // global gate column

    // ---- U column pre-packed, PERMUTED: up[0..31] = my-half rows (d0..d0+63),
    //      up[32..63] = peer-half rows. Static indexing in both GEMV halves.
    ull up[H_ / 2];
    #pragma unroll
    for (int q = 0; q < 32; ++q)
        up[q] = pk2(U[(size_t)(d0 + 2 * q) * G_ + gc],
                    U[(size_t)(d0 + 2 * q + 1) * G_ + gc]);
    #pragma unroll
    for (int q = 0; q < 32; ++q)
        up[32 + q] = pk2(U[(size_t)(pd0 + 2 * q) * G_ + gc],
                         U[(size_t)(pd0 + 2 * q + 1) * G_ + gc]);

    const int ej = tid >> 6;                 // seq (0..3)
    const int ed = tid & 63;                 // my local dim (0..63)
    const unsigned peer = rank ^ 1;

    // mbarriers: tx-only — count=1 (tid0's expect_tx arrive), 1024 tx bytes/phase
    const unsigned bar0 = smem_u32(sm);
    const unsigned bar1 = bar0 + 8;
    if (tid == 0) { MBAR_INIT(bar0, 1); MBAR_INIT(bar1, 1); }
    __syncthreads();
    CLUSTER_SYNC();   // peer bars initialized before any st.async targets them

    const unsigned mybar[2]  = { bar0, bar1 };
    const unsigned pbar[2]   = { mapa_peer(bar0, peer), mapa_peer(bar1, peer) };
    const unsigned slot0 = smem_u32(hsumP) + (unsigned)((ej * H_ + d0 + ed) * 4);
    const unsigned slot1 = slot0 + (unsigned)(NB * H_ * 4);
    const unsigned myslot[2] = { slot0, slot1 };
    const unsigned pslot[2]  = { mapa_peer(slot0, peer), mapa_peer(slot1, peer) };

    float hacc = 0.0f, lsum = 0.0f;

    for (int k = 0; k < NBLK; ++k) {
        const int t0 = k * TB;
        const int plen = t0 + TB;

        // ---- topo prefix + mask (prior readers done at epilogue syncthreads) ----
        for (int r_ = wid; r_ < TB * NB; r_ += 8) {
            int tt = r_ / NB, j = r_ % NB;
            const float* src = topo + ((size_t)(t0 + tt) * N_ + (n0 + j)) * T_;
            for (int tp = lane; tp < plen; tp += 32)
                topoT[(j * 200 + tp) * 12 + tt] = __ldcs(src + tp);
        }
        if (tid < TB * NB) {
            int tt = tid >> 2, j = tid & 3;
            smask[tt * NB + j] = mask[(t0 + tt) * N_ + n0 + j];
        }
        __syncthreads();

        // ---- prologue: P[tt][j][my dims] from global history ----
        if (k == 0) {
            for (int i = tid; i < 2 * TB * NB * HD; i += 256) Ph[i] = 0.0f;
        } else {
            const int j  = wid >> 1;
            const int hc = wid & 1;
            const float* hist = hc ? g_chist : g_hhist;
            float* P = hc ? Pc : Ph;
            const int dl2 = lane * 2;
            ull acc[5][2];
            #pragma unroll
            for (int pr = 0; pr < 5; pr++) { acc[pr][0] = 0ull; acc[pr][1] = 0ull; }
            #pragma unroll 4
            for (int tp = 0; tp < t0; ++tp) {
                float2 hv = *(const float2*)(hist + ((size_t)tp * N_ + n0 + j) * H_ + d0 + dl2);
                const float* tr = topoT + (j * 200 + tp) * 12;
                ulonglong2 wA = *(const ulonglong2*)(tr);
                ulonglong2 wB = *(const ulonglong2*)(tr + 4);
                ull        wC = *(const ull*)(tr + 8);
                ull h0 = pk2(hv.x, hv.x), h1 = pk2(hv.y, hv.y);
                acc[0][0] = f2fma(wA.x, h0, acc[0][0]); acc[0][1] = f2fma(wA.x, h1, acc[0][1]);
                acc[1][0] = f2fma(wA.y, h0, acc[1][0]); acc[1][1] = f2fma(wA.y, h1, acc[1][1]);
                acc[2][0] = f2fma(wB.x, h0, acc[2][0]); acc[2][1] = f2fma(wB.x, h1, acc[2][1]);
                acc[3][0] = f2fma(wB.y, h0, acc[3][0]); acc[3][1] = f2fma(wB.y, h1, acc[3][1]);
                acc[4][0] = f2fma(wC,   h0, acc[4][0]); acc[4][1] = f2fma(wC,   h1, acc[4][1]);
            }
            #pragma unroll
            for (int pr = 0; pr < 5; pr++) {
                float2 a0 = up2(acc[pr][0]);
                float2 a1 = up2(acc[pr][1]);
                P[((2 * pr)     * NB + j) * HD + dl2]     = a0.x;
                P[((2 * pr + 1) * NB + j) * HD + dl2]     = a0.y;
                P[((2 * pr)     * NB + j) * HD + dl2 + 1] = a1.x;
                P[((2 * pr + 1) * NB + j) * HD + dl2 + 1] = a1.y;
            }
        }
        __syncthreads();

        // ---- publish for tt=0 of this block (buf = t0&1 = 0 since TB even) ----
        float ac_cur;
        {
            const int b0 = t0 & 1;
            float ah = Ph[(0 * NB + ej) * HD + ed];
            ac_cur   = Pc[(0 * NB + ej) * HD + ed];
            asm volatile("st.shared.f32 [%0], %1;" :: "r"(myslot[b0]), "f"(ah) : "memory");
            stasync_peer(pslot[b0], ah, pbar[b0]);
            if (tid == 0) MBAR_EXPECT_TX(mybar[b0], 1024);
        }

        // ---- sequential steps ----
        for (int tt = 0; tt < TB; ++tt) {
            const int t = t0 + tt;
            const int buf = t & 1;
            const unsigned par = (unsigned)((t >> 1) & 1);

            // prefetch Wx (consumed after the GEMV; hides under compute)
            const float* wbase = g_wx + ((size_t)t * N_ + n0) * G_ + gc;
            float w0 = __ldcs(wbase);
            float w1 = __ldcs(wbase + G_);
            float w2 = __ldcs(wbase + 2 * G_);
            float w3 = __ldcs(wbase + 3 * G_);
            float m  = smask[tt * NB + ej];

            __syncthreads();   // local hsum half visible CTA-wide

            ull acc0 = 0ull, acc1 = 0ull, acc2 = 0ull, acc3 = 0ull;
            const float* hb = hsumP + buf * NB * H_;

            // phase B1: GEMV over MY half — overlaps peer st.async flight
            {
                const float* hl = hb + d0;
                #pragma unroll
                for (int q4 = 0; q4 < 16; ++q4) {
                    ulonglong2 h0 = *(const ulonglong2*)(hl + 0 * H_ + q4 * 4);
                    ulonglong2 h1 = *(const ulonglong2*)(hl + 1 * H_ + q4 * 4);
                    ulonglong2 h2 = *(const ulonglong2*)(hl + 2 * H_ + q4 * 4);
                    ulonglong2 h3 = *(const ulonglong2*)(hl + 3 * H_ + q4 * 4);
                    ull ua = up[2 * q4], ub = up[2 * q4 + 1];
                    acc0 = f2fma(h0.x, ua, acc0); acc0 = f2fma(h0.y, ub, acc0);
                    acc1 = f2fma(h1.x, ua, acc1); acc1 = f2fma(h1.y, ub, acc1);
                    acc2 = f2fma(h2.x, ua, acc2); acc2 = f2fma(h2.y, ub, acc2);
                    acc3 = f2fma(h3.x, ua, acc3); acc3 = f2fma(h3.y, ub, acc3);
                }
            }

            MBAR_WAIT_PARITY_CLUSTER(mybar[buf], par);   // peer half arrived

            // phase B2: GEMV over PEER half
            {
                const float* hp = hb + pd0;
                #pragma unroll
                for (int q4 = 0; q4 < 16; ++q4) {
                    ulonglong2 h0 = *(const ulonglong2*)(hp + 0 * H_ + q4 * 4);
                    ulonglong2 h1 = *(const ulonglong2*)(hp + 1 * H_ + q4 * 4);
                    ulonglong2 h2 = *(const ulonglong2*)(hp + 2 * H_ + q4 * 4);
                    ulonglong2 h3 = *(const ulonglong2*)(hp + 3 * H_ + q4 * 4);
                    ull ua = up[32 + 2 * q4], ub = up[33 + 2 * q4];
                    acc0 = f2fma(h0.x, ua, acc0); acc0 = f2fma(h0.y, ub, acc0);
                    acc1 = f2fma(h1.x, ua, acc1); acc1 = f2fma(h1.y, ub, acc1);
                    acc2 = f2fma(h2.x, ua, acc2); acc2 = f2fma(h2.y, ub, acc2);
                    acc3 = f2fma(h3.x, ua, acc3); acc3 = f2fma(h3.y, ub, acc3);
                }
            }

            {
                float2 p0 = up2(acc0), p1 = up2(acc1), p2 = up2(acc2), p3 = up2(acc3);
                gl[0 * 256 + lc] = p0.x + p0.y + w0;
                gl[1 * 256 + lc] = p1.x + p1.y + w1;
                gl[2 * 256 + lc] = p2.x + p2.y + w2;
                gl[3 * 256 + lc] = p3.x + p3.y + w3;
            }
            __syncthreads();

            // phase C + A(tt+1): cell, self-owned ring writes, next agg, publish
            {
                float ig = fsig(gl[ej * 256 + ed]);
                float fg = fsig(gl[ej * 256 + 64 + ed]);
                float og = fsig(gl[ej * 256 + 128 + ed]);
                float gt = ftanh(gl[ej * 256 + 192 + ed]);
                float c  = m * (fg * ac_cur + ig * gt);
                float h  = m * (og * ftanh(c));
                ringh[(tt * NB + ej) * HD + ed] = h;
                ringc[(tt * NB + ej) * HD + ed] = c;
                hacc += m * h;
                lsum += m;

                if (tt + 1 < TB) {
                    const int nbuf = (t + 1) & 1;
                    float ah = Ph[((tt + 1) * NB + ej) * HD + ed];
                    ac_cur   = Pc[((tt + 1) * NB + ej) * HD + ed];
                    const float* tb2 = topoT + (ej * 200 + t0) * 12 + (tt + 1);
                    for (int s = 0; s <= tt; ++s) {
                        float w = tb2[s * 12];
                        ah     += w * ringh[(s * NB + ej) * HD + ed];
                        ac_cur += w * ringc[(s * NB + ej) * HD + ed];
                    }
                    asm volatile("st.shared.f32 [%0], %1;" :: "r"(myslot[nbuf]), "f"(ah) : "memory");
                    stasync_peer(pslot[nbuf], ah, pbar[nbuf]);
                    if (tid == 0) MBAR_EXPECT_TX(mybar[nbuf], 1024);
                }
            }
        }

        // ---- block epilogue: flush ring to global history (batched) ----
        #pragma unroll
        for (int s = 0; s < TB; ++s) {
            g_hhist[((size_t)(t0 + s) * N_ + n0 + ej) * H_ + d0 + ed] =
                ringh[(s * NB + ej) * HD + ed];
            g_chist[((size_t)(t0 + s) * N_ + n0 + ej) * H_ + d0 + ed] =
                ringc[(s * NB + ej) * HD + ed];
        }
        __syncthreads();   // flush visible + topoT readers done before next block
    }

    g_hmean[(n0 + ej) * H_ + d0 + ed] = hacc / lsum;
    CLUSTER_SYNC();   // no CTA exits while peer st.async may be in flight
}

// ---------------------------------------------------------------------------
// Kernel 3: out = h_mean @ W_out + b_out   (4x4 tile, k-quad vectorized As)
// ---------------------------------------------------------------------------
__global__ void __launch_bounds__(256) out_kernel(const float* __restrict__ Wout,
                                                  const float* __restrict__ bout,
                                                  float* __restrict__ out)
{
    extern __shared__ float sm[];
    float* As = sm;                 // [64][132]
    float* Bs = sm + 64 * 132;      // [128][64]

    const int tid = threadIdx.x;
    const int bc = blockIdx.x;
    const int br = blockIdx.y;
    const int cbase = bc * 64;

    for (int p = tid; p < 64 * 32; p += 256) {
        int r = p >> 5, kq = p & 31;
        float4 v = *(const float4*)(g_hmean + (size_t)(br * 64 + r) * H_ + kq * 4);
        float* dst = As + r * 132 + kq * 4;
        dst[0] = v.x; dst[1] = v.y; dst[2] = v.z; dst[3] = v.w;
    }
    for (int p = tid; p < 128 * 16; p += 256) {
        int k = p >> 4, cq = p & 15;
        int c = cbase + cq * 4;
        float4 v = make_float4(0.f, 0.f, 0.f, 0.f);
        if (c < V_) v = *(const float4*)(Wout + (size_t)k * V_ + c);
        *(float4*)(Bs + k * 64 + cq * 4) = v;
    }
    __syncthreads();

    const int ty = tid >> 4, tx = tid & 15;
    const int r0 = ty * 4, c0 = tx * 4;
    ull a01[4], a23[4];
    #pragma unroll
    for (int i = 0; i < 4; i++) { a01[i] = 0ull; a23[i] = 0ull; }

    #pragma unroll 4
    for (int k4 = 0; k4 < 32; ++k4) {
        const int kb = k4 * 4;
        float a[4][4];
        #pragma unroll
        for (int i = 0; i < 4; i++)
            *(float4*)a[i] = *(const float4*)(As + (r0 + i) * 132 + kb);
        #pragma unroll
        for (int kk = 0; kk < 4; ++kk) {
            ulonglong2 bv = *(const ulonglong2*)(Bs + (kb + kk) * 64 + c0);
            #pragma unroll
            for (int i = 0; i < 4; i++) {
                ull ap = pk2(a[i][kk], a[i][kk]);
                a01[i] = f2fma(ap, bv.x, a01[i]);
                a23[i] = f2fma(ap, bv.y, a23[i]);
            }
        }
    }

    int c = cbase + c0;
    if (c < V_) {
        float4 bias = *(const float4*)(bout + c);
        #pragma unroll
        for (int i = 0; i < 4; i++) {
            int row = br * 64 + r0 + i;
            float2 p01 = up2(a01[i]), p23 = up2(a23[i]);
            float4 o;
            o.x = p01.x + bias.x;
            o.y = p01.y + bias.y;
            o.z = p23.x + bias.z;
            o.w = p23.y + bias.w;
            *(float4*)(out + (size_t)row * V_ + c) = o;
        }
    }
}

// ---------------------------------------------------------------------------
extern "C" void kernel_launch(void* const* d_in, const int* in_sizes, int n_in,
                              void* d_out, int out_size)
{
    const int*   seq  = (const int*)d_in[0];
    const float* mask = (const float*)d_in[1];
    const float* topo = (const float*)d_in[2];
    const float* W    = (const float*)d_in[3];
    const float* U    = (const float*)d_in[4];
    const float* b    = (const float*)d_in[5];
    const float* emb  = (const float*)d_in[6];
    const float* Wout = (const float*)d_in[7];
    const float* bout = (const float*)d_in[8];
    float* out = (float*)d_out;

    const int smem_gemm = (64 * 132 + 128 * 64 + 64) * 4;     // 66,816 B
    const int smem_rec  = (4 + 4 * 200 * 12 + 4 * TB * NB * HD
                           + 2 * NB * H_ + NB * 256 + TB * NB + 16) * 4;  // ~88 KB

    cudaFuncSetAttribute(wx_kernel,   cudaFuncAttributeMaxDynamicSharedMemorySize, smem_gemm);
    cudaFuncSetAttribute(out_kernel,  cudaFuncAttributeMaxDynamicSharedMemorySize, smem_gemm);
    cudaFuncSetAttribute(rec8_kernel, cudaFuncAttributeMaxDynamicSharedMemorySize, smem_rec);

    wx_kernel<<<dim3(G_ / 64, (T_ * N_) / 64), 256, smem_gemm>>>(seq, emb, W, b);
    rec8_kernel<<<2 * NCLUST, 256, smem_rec>>>(mask, topo, U);
    out_kernel<<<dim3((V_ + 63) / 64, N_ / 64), 256, smem_gemm>>>(Wout, bout, out);
}